// round 13
// baseline (speedup 1.0000x reference)
#include <cuda_runtime.h>
#include <cuda_fp16.h>
#include <cstdint>
#include <math_constants.h>

#define DD 128
#define NN 8192
#define KK 256
#define RQPAD 8704         // front-aligned pair rows: row d spans e in [8*(d/8), 128)
#define RTOT 8832          // + 128 linear rows  (= 138 * 64)
#define NSEG 1104          // RTOT / 8
#define SEGSPLIT 4
#define SEGPB (NSEG / SEGSPLIT)   // 276
#define XROW 136           // halves per xs2 row (128 + 1.0 marker + zeros)
#define KC 64              // k-chunk (halves)
#define NCH (RTOT / KC)    // 138
#define NST 6              // pipeline stages (prefetch distance 5)
#define STAGE_BYTES 32768  // 16KB A + 16KB B per stage

// ------------- device scratch (no allocations allowed) ---------------------
__device__ __align__(16) float  g_At[KK * DD * DD];      // A_c row-major per c (16 MB)
__device__ __align__(16) __half g_C[(size_t)KK * RTOT];  // coeff matrix fp16
__device__ __align__(16) __half g_F[(size_t)NN * RTOT];  // feature matrix fp16 (145 MB)
__device__ __align__(16) float  g_sq[(size_t)KK * NN];   // sq, c-major
__device__ float g_kc[KK];                               // per-c constant
__device__ __align__(16) unsigned short g_lut[NSEG];     // seg -> (d<<8)|e0 (e0 8-aligned)
__device__ int g_rowbase[129];                           // padded prefix sums

// ------------------------------- PTX helpers -------------------------------
__device__ __forceinline__ uint32_t smem_u32(const void* p) {
    uint32_t a;
    asm("{ .reg .u64 t; cvta.to.shared.u64 t, %1; cvt.u32.u64 %0, t; }"
        : "=r"(a) : "l"(p));
    return a;
}
__device__ __forceinline__ void cp16h(uint32_t dst, const __half* src) {
    asm volatile("cp.async.cg.shared.global [%0], [%1], 16;"
                 :: "r"(dst), "l"((unsigned long long)__cvta_generic_to_global(src)));
}
#define CP_COMMIT() asm volatile("cp.async.commit_group;" ::: "memory")
#define CP_WAIT4()  asm volatile("cp.async.wait_group 4;" ::: "memory")

__device__ __forceinline__ void ldsm4(uint32_t* r, uint32_t addr) {
    asm volatile("ldmatrix.sync.aligned.m8n8.x4.shared.b16 {%0,%1,%2,%3}, [%4];"
                 : "=r"(r[0]), "=r"(r[1]), "=r"(r[2]), "=r"(r[3]) : "r"(addr));
}
__device__ __forceinline__ void mma16816(float* c, const uint32_t* a,
                                         uint32_t b0, uint32_t b1) {
    asm volatile(
        "mma.sync.aligned.m16n8k16.row.col.f32.f16.f16.f32 "
        "{%0,%1,%2,%3}, {%4,%5,%6,%7}, {%8,%9}, {%0,%1,%2,%3};"
        : "+f"(c[0]), "+f"(c[1]), "+f"(c[2]), "+f"(c[3])
        : "r"(a[0]), "r"(a[1]), "r"(a[2]), "r"(a[3]), "r"(b0), "r"(b1));
}

// ---------------------------------------------------------------------------
// Kernel 0: transpose N_A (16384 x 256) -> At (256 x 16384); block (0,0)
// additionally builds the rowbase prefix sums + segment LUT.
// ---------------------------------------------------------------------------
__global__ void transpose_kernel(const float* __restrict__ NA) {
    __shared__ float t[32][33];
    __shared__ int srb[129];
    int r0 = blockIdx.x * 32;
    int c0 = blockIdx.y * 32;
    int tx = threadIdx.x, ty = threadIdx.y;

    if (blockIdx.x == 0 && blockIdx.y == 0) {   // LUT duty
        int tid = ty * 32 + tx;
        if (tid == 0) {
            int acc = 0;
            for (int d = 0; d < 128; d++) {
                srb[d] = acc;
                acc += 128 - 8 * (d >> 3);
            }
            srb[128] = acc;                     // 8704
        }
        __syncthreads();
        if (tid < 129) g_rowbase[tid] = srb[tid];
        if (tid < 128) {
            int d = tid, fd = d >> 3;
            int sb2 = srb[d] / 8, ns = 16 - fd;
            for (int s = 0; s < ns; s++)
                g_lut[sb2 + s] = (unsigned short)((d << 8) | (8 * (fd + s)));
        } else if (tid < 144) {
            int s = tid - 128;                  // 16 linear segments (marker 128)
            g_lut[RQPAD / 8 + s] = (unsigned short)((128 << 8) | (s * 8));
        }
        __syncthreads();
    }

#pragma unroll
    for (int i = ty; i < 32; i += 8)
        t[i][tx] = NA[(r0 + i) * KK + c0 + tx];
    __syncthreads();
#pragma unroll
    for (int i = ty; i < 32; i += 8)
        g_At[(size_t)(c0 + i) * (DD * DD) + r0 + tx] = t[tx][i];
}

// ---------------------------------------------------------------------------
// Kernel 1: per-c coefficients. G_c = A_c^T A_c (upper tiles only), w_c, k_c.
// ---------------------------------------------------------------------------
__global__ __launch_bounds__(256, 2) void gbuild_kernel(const float* __restrict__ mu) {
    extern __shared__ float sm[];
    float* sA  = sm;                   // [128][132]
    float* smu = sm + 128 * 132;       // [128]
    float* ss  = smu + 128;            // [128]
    int*   srb = (int*)(ss + 128);     // [129]
    const int c = blockIdx.x, tid = threadIdx.x;

    const float* Ac = g_At + (size_t)c * (DD * DD);
    for (int i = tid * 4; i < DD * DD; i += 1024) {
        float4 v = *(const float4*)(Ac + i);
        int k = i >> 7, e = i & 127;
        *(float4*)(sA + k * 132 + e) = v;
    }
    if (tid < DD) smu[tid] = mu[tid * KK + c];
    if (tid < 129) srb[tid] = g_rowbase[tid];
    __syncthreads();

    if (tid < DD) {                    // s[k] = A_c row k . mu
        float s = 0.f;
#pragma unroll 8
        for (int e = 0; e < DD; e++) s += sA[tid * 132 + e] * smu[e];
        ss[tid] = s;
    }
    __syncthreads();
    if (tid < DD) {                    // w[d] = sum_k A[k][d] s[k]
        float w = 0.f;
#pragma unroll 8
        for (int k = 0; k < DD; k++) w += sA[k * 132 + tid] * ss[k];
        g_C[(size_t)c * RTOT + RQPAD + tid] = __float2half(-2.f * w);
    }
    if (tid == 0) {                    // k_c = ||s||^2
        float kk = 0.f;
        for (int k = 0; k < DD; k++) kk += ss[k] * ss[k];
        g_kc[c] = kk;
    }

    // G = A^T A; only tiles with tx >= ty do work (upper triangle + diagonal)
    const int tx = tid & 15, ty = tid >> 4;
    float acc[8][8] = {};
    if (tx >= ty) {
#pragma unroll 4
        for (int k = 0; k < DD; k++) {
            float a[8], b[8];
            *(float4*)(a)     = *(const float4*)(sA + k * 132 + ty * 8);
            *(float4*)(a + 4) = *(const float4*)(sA + k * 132 + ty * 8 + 4);
            *(float4*)(b)     = *(const float4*)(sA + k * 132 + tx * 8);
            *(float4*)(b + 4) = *(const float4*)(sA + k * 132 + tx * 8 + 4);
#pragma unroll
            for (int i = 0; i < 8; i++)
#pragma unroll
                for (int j = 0; j < 8; j++)
                    acc[i][j] += a[i] * b[j];
        }
        __half* Crow = g_C + (size_t)c * RTOT;
#pragma unroll
        for (int i = 0; i < 8; i++) {
            int d = ty * 8 + i;
            int base = srb[d] - 8 * ty;    // index = srb[d] + e - 8*(d>>3)
#pragma unroll
            for (int j = 0; j < 8; j++) {
                int e = tx * 8 + j;
                float v = (e < d) ? 0.f : (e == d ? 1.f : 2.f) * acc[i][j];
                Crow[base + e] = __float2half(v);
            }
        }
    }
}

// ---------------------------------------------------------------------------
// Kernel 2: feature matrix F, aligned-segment layout.
// ---------------------------------------------------------------------------
__global__ __launch_bounds__(256) void fbuild_kernel(const float* __restrict__ X) {
    __shared__ __align__(16) __half xs2[32 * XROW];
    __shared__ __align__(4) unsigned short slut[SEGPB];
    const int tid = threadIdx.x, lane = tid & 31, warp = tid >> 5;
    const int n0 = blockIdx.x * 32;
    const int sb = blockIdx.y * SEGPB;

#pragma unroll
    for (int it = 0; it < 2; it++) {
        int e0 = (warp + 8 * it) * 8;
        float v[8];
#pragma unroll
        for (int j = 0; j < 8; j++) v[j] = X[(size_t)(e0 + j) * NN + n0 + lane];
        __half2 h[4];
#pragma unroll
        for (int k = 0; k < 4; k++) h[k] = __floats2half2_rn(v[2 * k], v[2 * k + 1]);
        *(uint4*)(xs2 + lane * XROW + e0) = *(uint4*)h;
    }
    if (tid < 32 * 8) {
        int nl = tid >> 3, j = tid & 7;
        xs2[nl * XROW + 128 + j] = (j == 0) ? __float2half(1.0f) : __half(0);
    }
    for (int i = tid; i < SEGPB; i += 256) slut[i] = g_lut[sb + i];
    __syncthreads();

    for (int nl = 0; nl < 32; nl++) {
        const __half* xrow = xs2 + nl * XROW;
        __half* dst = g_F + (size_t)(n0 + nl) * RTOT + sb * 8;
        for (int s = tid; s < SEGPB; s += 256) {
            unsigned short lw = slut[s];
            int d = lw >> 8, e0 = lw & 255;
            __half2 xd2 = __half2half2(xrow[d]);
            __half2 xe[4];
            *(uint4*)xe = *(const uint4*)(xrow + e0);
            __half2 o[4];
#pragma unroll
            for (int k = 0; k < 4; k++) o[k] = __hmul2(xe[k], xd2);
            *(uint4*)(dst + s * 8) = *(uint4*)o;
        }
    }
}

// ---------------------------------------------------------------------------
// Kernel 3: fp16 mma.sync GEMM  sq[c,n] = sum_r C[c,r] * F[n,r]
// 8 warps (256 thr), warp tile 32x64, CTA 128x128, 6-stage cp.async
// (prefetch distance 5), no split-k, 1 CTA/SM. Grid (2, 64) = 128 CTAs.
// ---------------------------------------------------------------------------
__global__ __launch_bounds__(256, 1) void mma_kernel() {
    extern __shared__ char dsm[];
    const uint32_t sbase = smem_u32(dsm);
    const int tid = threadIdx.x, lane = tid & 31, wid = tid >> 5;
    const int c0 = blockIdx.x * 128, n0 = blockIdx.y * 128;
    const int mwarp = wid & 3, nwarp = wid >> 2;

    auto load_stage = [&](int st, int ch) {
        uint32_t ab = sbase + st * STAGE_BYTES;
        uint32_t bb = ab + 16384;
        const __half* As = g_C + (size_t)c0 * RTOT + ch * KC;
        const __half* Bs = g_F + (size_t)n0 * RTOT + ch * KC;
#pragma unroll
        for (int j = 0; j < 4; j++) {
            int seg = tid + j * 256;          // 0..1023
            int row = seg >> 3, s = seg & 7;
            uint32_t off = (uint32_t)(row * 128 + ((s ^ (row & 7)) << 4));
            cp16h(ab + off, As + (size_t)row * RTOT + s * 8);
            cp16h(bb + off, Bs + (size_t)row * RTOT + s * 8);
        }
        CP_COMMIT();
    };

#pragma unroll
    for (int s = 0; s < NST - 1; s++) load_stage(s, s);

    float acc[2][8][4] = {};

    const int laneRow = lane & 7;
    const int grp = lane >> 3;               // 0..3
    const int rowOffA = (grp & 1) << 3;      // A: +8 rows for odd groups
    const int kgA = grp >> 1;                // A: +8 k for groups 2,3
    const int rowOffB = (lane >> 4) << 3;    // B: +8 n-rows for t16..31
    const int kgB = (lane >> 3) & 1;         // B: +8 k for groups 1,3
    const int mA = mwarp * 32, nB = nwarp * 64;

    for (int i = 0; i < NCH; i++) {
        CP_WAIT4();                // my groups for chunk i retired (in-order)
        __syncthreads();           // all warps done reading stage (i-1)%NST
        if (i + NST - 1 < NCH) load_stage((i + NST - 1) % NST, i + NST - 1);
        else CP_COMMIT();          // empty group keeps accounting consistent

        uint32_t ab = sbase + (i % NST) * STAGE_BYTES;
        uint32_t bb = ab + 16384;
#pragma unroll
        for (int ks = 0; ks < 4; ks++) {
            uint32_t a[2][4], b[4][4];
#pragma unroll
            for (int m = 0; m < 2; m++) {
                int row = mA + 16 * m + laneRow + rowOffA;
                uint32_t addr = ab + (uint32_t)(row * 128 +
                                (((ks * 2 + kgA) ^ laneRow) << 4));
                ldsm4(a[m], addr);
            }
#pragma unroll
            for (int j = 0; j < 4; j++) {
                int row = nB + 16 * j + laneRow + rowOffB;
                uint32_t addr = bb + (uint32_t)(row * 128 +
                                (((ks * 2 + kgB) ^ laneRow) << 4));
                ldsm4(b[j], addr);
            }
#pragma unroll
            for (int m = 0; m < 2; m++)
#pragma unroll
                for (int t = 0; t < 8; t++)
                    mma16816(acc[m][t], a[m],
                             b[t >> 1][(t & 1) << 1],
                             b[t >> 1][((t & 1) << 1) + 1]);
        }
    }

    const int crow = c0 + mA + (lane >> 2);
    const int ncol = n0 + nB + ((lane & 3) << 1);
#pragma unroll
    for (int m = 0; m < 2; m++) {
#pragma unroll
        for (int t = 0; t < 8; t++) {
            float2 v0 = make_float2(acc[m][t][0], acc[m][t][1]);
            float2 v1 = make_float2(acc[m][t][2], acc[m][t][3]);
            *(float2*)(g_sq + (size_t)(crow + 16 * m)     * NN + ncol + 8 * t) = v0;
            *(float2*)(g_sq + (size_t)(crow + 16 * m + 8) * NN + ncol + 8 * t) = v1;
        }
    }
}

// ---------------------------------------------------------------------------
// Kernel 4: softmax over c; logits = gamma*(sq + k_c); writes Pi rows.
// ---------------------------------------------------------------------------
__global__ __launch_bounds__(256) void softmax_kernel(const float* __restrict__ gamma_p,
                                                      float* __restrict__ out) {
    __shared__ float tile[32 * 257];
    __shared__ float sk[KK];
    const float g = *gamma_p;
    const int n0 = blockIdx.x * 32;
    const int tid = threadIdx.x;

    for (int i = tid; i < KK; i += 256) sk[i] = g_kc[i];
    for (int i = tid; i < 32 * KK; i += 256) {
        int cc = i >> 5, nl = i & 31;
        tile[nl * 257 + cc] = g_sq[(size_t)cc * NN + n0 + nl];
    }
    __syncthreads();

    const int warp = tid >> 5, lane = tid & 31;
    for (int r = warp; r < 32; r += 8) {
        float v[8];
        float m = -CUDART_INF_F;
#pragma unroll
        for (int u = 0; u < 8; u++) {
            int c = lane + 32 * u;
            v[u] = g * (tile[r * 257 + c] + sk[c]);
            m = fmaxf(m, v[u]);
        }
#pragma unroll
        for (int o = 16; o > 0; o >>= 1)
            m = fmaxf(m, __shfl_xor_sync(0xffffffffu, m, o));
        float s = 0.f;
#pragma unroll
        for (int u = 0; u < 8; u++) {
            v[u] = __expf(v[u] - m);
            s += v[u];
        }
#pragma unroll
        for (int o = 16; o > 0; o >>= 1)
            s += __shfl_xor_sync(0xffffffffu, s, o);
        float inv = __frcp_rn(s);
#pragma unroll
        for (int u = 0; u < 8; u++)
            tile[r * 257 + lane + 32 * u] = v[u] * inv;
    }
    __syncthreads();

    for (int i = tid; i < 32 * KK; i += 256) {
        int c = i >> 5, j = i & 31;
        out[(size_t)(DD + c) * NN + n0 + j] = tile[j * 257 + c];
    }
}

// ---------------------------------------------------------------------------
extern "C" void kernel_launch(void* const* d_in, const int* in_sizes, int n_in,
                              void* d_out, int out_size) {
    const float* X     = (const float*)d_in[0];  // (D, N)
    const float* NA    = (const float*)d_in[1];  // (D, D, K)
    const float* Nmu   = (const float*)d_in[2];  // (D, K)
    const float* gamma = (const float*)d_in[3];  // scalar
    float* out = (float*)d_out;                  // (D+K, N)

    cudaFuncSetAttribute(gbuild_kernel, cudaFuncAttributeMaxDynamicSharedMemorySize,
                         (128 * 132 + 128 + 128 + 132) * 4 + 256);
    cudaFuncSetAttribute(mma_kernel, cudaFuncAttributeMaxDynamicSharedMemorySize,
                         NST * STAGE_BYTES);

    // rows 0..D-1 of out = X verbatim
    cudaMemcpyAsync(out, X, (size_t)DD * NN * sizeof(float),
                    cudaMemcpyDeviceToDevice, 0);

    transpose_kernel<<<dim3((DD * DD) / 32, KK / 32), dim3(32, 8)>>>(NA);
    gbuild_kernel<<<KK, 256, (128 * 132 + 128 + 128 + 132) * 4 + 256>>>(Nmu);
    fbuild_kernel<<<dim3(NN / 32, SEGSPLIT), 256>>>(X);
    mma_kernel<<<dim3(2, 64), 256, NST * STAGE_BYTES>>>();
    softmax_kernel<<<NN / 32, 256>>>(gamma, out);
}

// round 17
// speedup vs baseline: 1.1558x; 1.1558x over previous
#include <cuda_runtime.h>
#include <cuda_fp16.h>
#include <cstdint>
#include <math_constants.h>

#define DD 128
#define NN 8192
#define KK 256
#define RQPAD 8704         // front-aligned pair rows: row d spans e in [8*(d/8), 128)
#define RTOT 8832          // + 128 linear rows  (= 138 * 64)
#define NSEG 1104          // RTOT / 8
#define SEGSPLIT 4
#define SEGPB (NSEG / SEGSPLIT)   // 276
#define XROW 136           // halves per xs2 row (128 + 1.0 marker + zeros)
#define KC 64              // k-chunk (halves)
#define NCH (RTOT / KC)    // 138
#define KSPLIT 2
#define NST 3              // stage buffers
#define STAGE_BYTES 32768  // 16KB A + 16KB B per stage

// ------------- device scratch (no allocations allowed) ---------------------
__device__ __align__(16) float  g_At[KK * DD * DD];      // A_c row-major per c (16 MB)
__device__ __align__(16) __half g_C[(size_t)KK * RTOT];  // coeff matrix fp16
__device__ __align__(16) __half g_F[(size_t)NN * RTOT];  // feature matrix fp16 (145 MB)
__device__ __align__(16) float  g_sq[(size_t)KSPLIT * KK * NN]; // sq partials
__device__ float g_kc[KK];                               // per-c constant
__device__ __align__(16) unsigned short g_lut[NSEG];     // seg -> (d<<8)|e0 (e0 8-aligned)
__device__ int g_rowbase[129];                           // padded prefix sums

// ------------------------------- PTX helpers -------------------------------
__device__ __forceinline__ uint32_t smem_u32(const void* p) {
    uint32_t a;
    asm("{ .reg .u64 t; cvta.to.shared.u64 t, %1; cvt.u32.u64 %0, t; }"
        : "=r"(a) : "l"(p));
    return a;
}
__device__ __forceinline__ void cp16h(uint32_t dst, const __half* src) {
    asm volatile("cp.async.cg.shared.global [%0], [%1], 16;"
                 :: "r"(dst), "l"((unsigned long long)__cvta_generic_to_global(src)));
}
// .noinc: async arrival consumes one slot of the initialized count (256/stage).
// Without .noinc the arrive self-balances (inc then dec) and the barrier
// never completes -> the R16 deadlock.
#define CP_MBAR_ARRIVE(a) \
    asm volatile("cp.async.mbarrier.arrive.noinc.shared::cta.b64 [%0];" :: "r"(a) : "memory")
#define MBARRIER_INIT(a, n) \
    asm volatile("mbarrier.init.shared.b64 [%0], %1;" :: "r"(a), "r"((uint32_t)(n)) : "memory")
#define MBARRIER_INVAL(a) \
    asm volatile("mbarrier.inval.shared.b64 [%0];" :: "r"(a) : "memory")
#define MBARRIER_ARRIVE(a) \
    asm volatile("mbarrier.arrive.shared.b64 _, [%0];" :: "r"(a) : "memory")
#define MBAR_WAIT(a, ph) do {                                                  \
    uint32_t _m = (a), _p = (uint32_t)(ph), _d;                                \
    asm volatile("{\n\t.reg .pred p;\n\t"                                      \
        "mbarrier.try_wait.parity.acquire.cta.shared::cta.b64 p, [%1], %2;\n\t"\
        "selp.b32 %0, 1, 0, p;\n\t}" : "=r"(_d) : "r"(_m), "r"(_p) : "memory");\
    if (!_d) {                                                                 \
        asm volatile("{\n\t.reg .pred P1;\n\t"                                 \
        "WL_%=:\n\t"                                                           \
        "mbarrier.try_wait.parity.acquire.cta.shared::cta.b64 P1, [%0], %1, 0x989680;\n\t" \
        "@P1 bra.uni WD_%=;\n\t"                                               \
        "bra.uni WL_%=;\n\t"                                                   \
        "WD_%=:\n\t}" :: "r"(_m), "r"(_p) : "memory");                         \
    }                                                                          \
} while (0)

__device__ __forceinline__ void ldsm4(uint32_t* r, uint32_t addr) {
    asm volatile("ldmatrix.sync.aligned.m8n8.x4.shared.b16 {%0,%1,%2,%3}, [%4];"
                 : "=r"(r[0]), "=r"(r[1]), "=r"(r[2]), "=r"(r[3]) : "r"(addr));
}
__device__ __forceinline__ void mma16816(float* c, const uint32_t* a,
                                         uint32_t b0, uint32_t b1) {
    asm volatile(
        "mma.sync.aligned.m16n8k16.row.col.f32.f16.f16.f32 "
        "{%0,%1,%2,%3}, {%4,%5,%6,%7}, {%8,%9}, {%0,%1,%2,%3};"
        : "+f"(c[0]), "+f"(c[1]), "+f"(c[2]), "+f"(c[3])
        : "r"(a[0]), "r"(a[1]), "r"(a[2]), "r"(a[3]), "r"(b0), "r"(b1));
}

// ---------------------------------------------------------------------------
// Kernel 0: transpose N_A (16384 x 256) -> At (256 x 16384); block (0,0)
// additionally builds the rowbase prefix sums + segment LUT.
// ---------------------------------------------------------------------------
__global__ void transpose_kernel(const float* __restrict__ NA) {
    __shared__ float t[32][33];
    __shared__ int srb[129];
    int r0 = blockIdx.x * 32;
    int c0 = blockIdx.y * 32;
    int tx = threadIdx.x, ty = threadIdx.y;

    if (blockIdx.x == 0 && blockIdx.y == 0) {   // LUT duty
        int tid = ty * 32 + tx;
        if (tid == 0) {
            int acc = 0;
            for (int d = 0; d < 128; d++) {
                srb[d] = acc;
                acc += 128 - 8 * (d >> 3);
            }
            srb[128] = acc;                     // 8704
        }
        __syncthreads();
        if (tid < 129) g_rowbase[tid] = srb[tid];
        if (tid < 128) {
            int d = tid, fd = d >> 3;
            int sb2 = srb[d] / 8, ns = 16 - fd;
            for (int s = 0; s < ns; s++)
                g_lut[sb2 + s] = (unsigned short)((d << 8) | (8 * (fd + s)));
        } else if (tid < 144) {
            int s = tid - 128;                  // 16 linear segments (marker 128)
            g_lut[RQPAD / 8 + s] = (unsigned short)((128 << 8) | (s * 8));
        }
        __syncthreads();
    }

#pragma unroll
    for (int i = ty; i < 32; i += 8)
        t[i][tx] = NA[(r0 + i) * KK + c0 + tx];
    __syncthreads();
#pragma unroll
    for (int i = ty; i < 32; i += 8)
        g_At[(size_t)(c0 + i) * (DD * DD) + r0 + tx] = t[tx][i];
}

// ---------------------------------------------------------------------------
// Kernel 1: per-c coefficients. G_c = A_c^T A_c (upper tiles only), w_c, k_c.
// ---------------------------------------------------------------------------
__global__ __launch_bounds__(256, 2) void gbuild_kernel(const float* __restrict__ mu) {
    extern __shared__ float sm[];
    float* sA  = sm;                   // [128][132]
    float* smu = sm + 128 * 132;       // [128]
    float* ss  = smu + 128;            // [128]
    int*   srb = (int*)(ss + 128);     // [129]
    const int c = blockIdx.x, tid = threadIdx.x;

    const float* Ac = g_At + (size_t)c * (DD * DD);
    for (int i = tid * 4; i < DD * DD; i += 1024) {
        float4 v = *(const float4*)(Ac + i);
        int k = i >> 7, e = i & 127;
        *(float4*)(sA + k * 132 + e) = v;
    }
    if (tid < DD) smu[tid] = mu[tid * KK + c];
    if (tid < 129) srb[tid] = g_rowbase[tid];
    __syncthreads();

    if (tid < DD) {                    // s[k] = A_c row k . mu
        float s = 0.f;
#pragma unroll 8
        for (int e = 0; e < DD; e++) s += sA[tid * 132 + e] * smu[e];
        ss[tid] = s;
    }
    __syncthreads();
    if (tid < DD) {                    // w[d] = sum_k A[k][d] s[k]
        float w = 0.f;
#pragma unroll 8
        for (int k = 0; k < DD; k++) w += sA[k * 132 + tid] * ss[k];
        g_C[(size_t)c * RTOT + RQPAD + tid] = __float2half(-2.f * w);
    }
    if (tid == 0) {                    // k_c = ||s||^2
        float kk = 0.f;
        for (int k = 0; k < DD; k++) kk += ss[k] * ss[k];
        g_kc[c] = kk;
    }

    // G = A^T A; only tiles with tx >= ty do work (upper triangle + diagonal)
    const int tx = tid & 15, ty = tid >> 4;
    float acc[8][8] = {};
    if (tx >= ty) {
#pragma unroll 4
        for (int k = 0; k < DD; k++) {
            float a[8], b[8];
            *(float4*)(a)     = *(const float4*)(sA + k * 132 + ty * 8);
            *(float4*)(a + 4) = *(const float4*)(sA + k * 132 + ty * 8 + 4);
            *(float4*)(b)     = *(const float4*)(sA + k * 132 + tx * 8);
            *(float4*)(b + 4) = *(const float4*)(sA + k * 132 + tx * 8 + 4);
#pragma unroll
            for (int i = 0; i < 8; i++)
#pragma unroll
                for (int j = 0; j < 8; j++)
                    acc[i][j] += a[i] * b[j];
        }
        __half* Crow = g_C + (size_t)c * RTOT;
#pragma unroll
        for (int i = 0; i < 8; i++) {
            int d = ty * 8 + i;
            int base = srb[d] - 8 * ty;    // index = srb[d] + e - 8*(d>>3)
#pragma unroll
            for (int j = 0; j < 8; j++) {
                int e = tx * 8 + j;
                float v = (e < d) ? 0.f : (e == d ? 1.f : 2.f) * acc[i][j];
                Crow[base + e] = __float2half(v);
            }
        }
    }
}

// ---------------------------------------------------------------------------
// Kernel 2: feature matrix F, aligned-segment layout.
// ---------------------------------------------------------------------------
__global__ __launch_bounds__(256) void fbuild_kernel(const float* __restrict__ X) {
    __shared__ __align__(16) __half xs2[32 * XROW];
    __shared__ __align__(4) unsigned short slut[SEGPB];
    const int tid = threadIdx.x, lane = tid & 31, warp = tid >> 5;
    const int n0 = blockIdx.x * 32;
    const int sb = blockIdx.y * SEGPB;

#pragma unroll
    for (int it = 0; it < 2; it++) {
        int e0 = (warp + 8 * it) * 8;
        float v[8];
#pragma unroll
        for (int j = 0; j < 8; j++) v[j] = X[(size_t)(e0 + j) * NN + n0 + lane];
        __half2 h[4];
#pragma unroll
        for (int k = 0; k < 4; k++) h[k] = __floats2half2_rn(v[2 * k], v[2 * k + 1]);
        *(uint4*)(xs2 + lane * XROW + e0) = *(uint4*)h;
    }
    if (tid < 32 * 8) {
        int nl = tid >> 3, j = tid & 7;
        xs2[nl * XROW + 128 + j] = (j == 0) ? __float2half(1.0f) : __half(0);
    }
    for (int i = tid; i < SEGPB; i += 256) slut[i] = g_lut[sb + i];
    __syncthreads();

    for (int nl = 0; nl < 32; nl++) {
        const __half* xrow = xs2 + nl * XROW;
        __half* dst = g_F + (size_t)(n0 + nl) * RTOT + sb * 8;
        for (int s = tid; s < SEGPB; s += 256) {
            unsigned short lw = slut[s];
            int d = lw >> 8, e0 = lw & 255;
            __half2 xd2 = __half2half2(xrow[d]);
            __half2 xe[4];
            *(uint4*)xe = *(const uint4*)(xrow + e0);
            __half2 o[4];
#pragma unroll
            for (int k = 0; k < 4; k++) o[k] = __hmul2(xe[k], xd2);
            *(uint4*)(dst + s * 8) = *(uint4*)o;
        }
    }
}

// ---------------------------------------------------------------------------
// Kernel 3: fp16 mma.sync GEMM  sq[c,n] = sum_r C[c,r] * F[n,r]
// 8 warps, warp tile 32x64, CTA 128x128, 3 stages, split-k 2, 2 CTAs/SM.
// Mbarrier producer/consumer per stage (NO bulk __syncthreads in main loop):
// each warp loads its 1/8 slice, signals full[] via cp.async.mbarrier.arrive
// .noinc (counts against the 256 init), frees stages via empty[] arrivals.
// ---------------------------------------------------------------------------
__global__ __launch_bounds__(256, 2) void mma_kernel() {
    extern __shared__ char dsm[];
    const uint32_t sbase = smem_u32(dsm);
    const uint32_t hdr = sbase + NST * STAGE_BYTES;   // full[3]@+0, empty[3]@+24
    const int tid = threadIdx.x, lane = tid & 31, wid = tid >> 5;
    const int c0 = blockIdx.x * 128, n0 = blockIdx.y * 128;
    const int kv = blockIdx.z;
    const int cbase = kv * (NCH / 2);
    const int nch = NCH / 2;                 // 69 (divisible by 3)
    const int mwarp = wid & 3, nwarp = wid >> 2;

    if (tid == 0) {
#pragma unroll
        for (int s = 0; s < NST; s++) {
            MBARRIER_INIT(hdr + 8 * s, 256);       // full: one async arrive/thread
            MBARRIER_INIT(hdr + 24 + 8 * s, 8);    // empty: one arrive per warp
        }
    }
    __syncthreads();

    // per-warp slice loader: warp wid covers rows [wid*16, wid*16+16) of A and B
    auto load_slice = [&](int st, int ch) {
        uint32_t ab = sbase + st * STAGE_BYTES;
        uint32_t bb = ab + 16384;
        const __half* As = g_C + (size_t)c0 * RTOT + ch * KC;
        const __half* Bs = g_F + (size_t)n0 * RTOT + ch * KC;
#pragma unroll
        for (int j = 0; j < 4; j++) {
            int idx = lane + 32 * j;              // 0..127 within warp slice
            int row = wid * 16 + (idx >> 3), s = idx & 7;
            uint32_t off = (uint32_t)(row * 128 + ((s ^ (row & 7)) << 4));
            cp16h(ab + off, As + (size_t)row * RTOT + s * 8);
            cp16h(bb + off, Bs + (size_t)row * RTOT + s * 8);
        }
    };

    // preload chunks 0,1 into stages 0,1 (fresh stages: no empty wait)
    load_slice(0, cbase);
    CP_MBAR_ARRIVE(hdr + 0);
    load_slice(1, cbase + 1);
    CP_MBAR_ARRIVE(hdr + 8);

    float acc[2][8][4] = {};

    const int laneRow = lane & 7;
    const int grp = lane >> 3;               // 0..3
    const int rowOffA = (grp & 1) << 3;      // A: +8 rows for odd groups
    const int kgA = grp >> 1;                // A: +8 k for groups 2,3
    const int rowOffB = (lane >> 4) << 3;    // B: +8 n-rows for t16..31
    const int kgB = (lane >> 3) & 1;         // B: +8 k for groups 1,3
    const int mA = mwarp * 32, nB = nwarp * 64;

    int pph[NST] = {0, 0, 1};   // producer parities (stage 2 fresh -> 1)
    int cph[NST] = {0, 0, 0};   // consumer parities

#pragma unroll 3
    for (int i = 0; i < nch; i++) {
        const int s = i % 3, s2 = (i + 2) % 3;
        if (i + 2 < nch) {                       // produce chunk i+2
            MBAR_WAIT(hdr + 24 + 8 * s2, pph[s2]);
            pph[s2] ^= 1;
            load_slice(s2, cbase + i + 2);
            CP_MBAR_ARRIVE(hdr + 8 * s2);
        }

        MBAR_WAIT(hdr + 8 * s, cph[s]);          // chunk i fully resident
        cph[s] ^= 1;

        uint32_t ab = sbase + s * STAGE_BYTES;
        uint32_t bb = ab + 16384;
#pragma unroll
        for (int ks = 0; ks < 4; ks++) {
            uint32_t a[2][4], b[4][4];
#pragma unroll
            for (int m = 0; m < 2; m++) {
                int row = mA + 16 * m + laneRow + rowOffA;
                uint32_t addr = ab + (uint32_t)(row * 128 +
                                (((ks * 2 + kgA) ^ laneRow) << 4));
                ldsm4(a[m], addr);
            }
#pragma unroll
            for (int j = 0; j < 4; j++) {
                int row = nB + 16 * j + laneRow + rowOffB;
                uint32_t addr = bb + (uint32_t)(row * 128 +
                                (((ks * 2 + kgB) ^ laneRow) << 4));
                ldsm4(b[j], addr);
            }
#pragma unroll
            for (int m = 0; m < 2; m++)
#pragma unroll
                for (int t = 0; t < 8; t++)
                    mma16816(acc[m][t], a[m],
                             b[t >> 1][(t & 1) << 1],
                             b[t >> 1][((t & 1) << 1) + 1]);
        }

        if (lane == 0) MBARRIER_ARRIVE(hdr + 24 + 8 * s);  // stage s free
    }

    float* slab = g_sq + (size_t)kv * KK * NN;
    const int crow = c0 + mA + (lane >> 2);
    const int ncol = n0 + nB + ((lane & 3) << 1);
#pragma unroll
    for (int m = 0; m < 2; m++) {
#pragma unroll
        for (int t = 0; t < 8; t++) {
            float2 v0 = make_float2(acc[m][t][0], acc[m][t][1]);
            float2 v1 = make_float2(acc[m][t][2], acc[m][t][3]);
            *(float2*)(slab + (size_t)(crow + 16 * m)     * NN + ncol + 8 * t) = v0;
            *(float2*)(slab + (size_t)(crow + 16 * m + 8) * NN + ncol + 8 * t) = v1;
        }
    }

    __syncthreads();
    if (tid == 0) {
#pragma unroll
        for (int s = 0; s < 2 * NST; s++) MBARRIER_INVAL(hdr + 8 * s);
    }
}

// ---------------------------------------------------------------------------
// Kernel 4: softmax over c; logits = gamma*(sum of sq slabs + k_c).
// ---------------------------------------------------------------------------
__global__ __launch_bounds__(256) void softmax_kernel(const float* __restrict__ gamma_p,
                                                      float* __restrict__ out) {
    __shared__ float tile[32 * 257];
    __shared__ float sk[KK];
    const float g = *gamma_p;
    const int n0 = blockIdx.x * 32;
    const int tid = threadIdx.x;

    for (int i = tid; i < KK; i += 256) sk[i] = g_kc[i];
    for (int i = tid; i < 32 * KK; i += 256) {
        int cc = i >> 5, nl = i & 31;
        size_t off = (size_t)cc * NN + n0 + nl;
        float s = g_sq[off];
#pragma unroll
        for (int kv = 1; kv < KSPLIT; kv++)
            s += g_sq[(size_t)kv * KK * NN + off];
        tile[nl * 257 + cc] = s;
    }
    __syncthreads();

    const int warp = tid >> 5, lane = tid & 31;
    for (int r = warp; r < 32; r += 8) {
        float v[8];
        float m = -CUDART_INF_F;
#pragma unroll
        for (int u = 0; u < 8; u++) {
            int c = lane + 32 * u;
            v[u] = g * (tile[r * 257 + c] + sk[c]);
            m = fmaxf(m, v[u]);
        }
#pragma unroll
        for (int o = 16; o > 0; o >>= 1)
            m = fmaxf(m, __shfl_xor_sync(0xffffffffu, m, o));
        float s = 0.f;
#pragma unroll
        for (int u = 0; u < 8; u++) {
            v[u] = __expf(v[u] - m);
            s += v[u];
        }
#pragma unroll
        for (int o = 16; o > 0; o >>= 1)
            s += __shfl_xor_sync(0xffffffffu, s, o);
        float inv = __frcp_rn(s);
#pragma unroll
        for (int u = 0; u < 8; u++)
            tile[r * 257 + lane + 32 * u] = v[u] * inv;
    }
    __syncthreads();

    for (int i = tid; i < 32 * KK; i += 256) {
        int c = i >> 5, j = i & 31;
        out[(size_t)(DD + c) * NN + n0 + j] = tile[j * 257 + c];
    }
}

// ---------------------------------------------------------------------------
extern "C" void kernel_launch(void* const* d_in, const int* in_sizes, int n_in,
                              void* d_out, int out_size) {
    const float* X     = (const float*)d_in[0];  // (D, N)
    const float* NA    = (const float*)d_in[1];  // (D, D, K)
    const float* Nmu   = (const float*)d_in[2];  // (D, K)
    const float* gamma = (const float*)d_in[3];  // scalar
    float* out = (float*)d_out;                  // (D+K, N)

    cudaFuncSetAttribute(gbuild_kernel, cudaFuncAttributeMaxDynamicSharedMemorySize,
                         (128 * 132 + 128 + 128 + 132) * 4 + 256);
    cudaFuncSetAttribute(mma_kernel, cudaFuncAttributeMaxDynamicSharedMemorySize,
                         NST * STAGE_BYTES + 64);

    // rows 0..D-1 of out = X verbatim
    cudaMemcpyAsync(out, X, (size_t)DD * NN * sizeof(float),
                    cudaMemcpyDeviceToDevice, 0);

    transpose_kernel<<<dim3((DD * DD) / 32, KK / 32), dim3(32, 8)>>>(NA);
    gbuild_kernel<<<KK, 256, (128 * 132 + 128 + 128 + 132) * 4 + 256>>>(Nmu);
    fbuild_kernel<<<dim3(NN / 32, SEGSPLIT), 256>>>(X);
    mma_kernel<<<dim3(2, 64, KSPLIT), 256, NST * STAGE_BYTES + 64>>>();
    softmax_kernel<<<NN / 32, 256>>>(gamma, out);
}